// round 3
// baseline (speedup 1.0000x reference)
#include <cuda_runtime.h>

// CANN recurrent net, 14 iterations:
//   y_t = J @ s_{t-1};  U_t = y_t/recSum_{t-1} + Iext;  s_t = (0.2 U_t)^2;
//   recSum_t = K * sum(s_t)
// Outputs: U_14 (1680), recSum_14 (1), r_14 = s_14/recSum_14 (1680)
//
// Persistent grid (148 blocks, 1/SM). J rows register-resident.
// Grid sync: per-block 64B chunk [s0..s11 | partial | tag], parity-buffered,
// tag monotonic across graph replays. Single release-store publisher per block.

#define Nn     1680
#define NB     148
#define TPB    384
#define NWARP  12
#define ITERS  14
#define KC     0.005f

__device__ float g_pub[2][NB][16];   // 64B chunk per block per parity

__device__ __forceinline__ unsigned long long ld_acq64(const void* p) {
    unsigned long long v;
    asm volatile("ld.acquire.gpu.global.u64 %0, [%1];" : "=l"(v) : "l"(p));
    return v;
}
__device__ __forceinline__ void st_rel64(void* p, unsigned long long v) {
    asm volatile("st.release.gpu.global.u64 [%0], %1;" :: "l"(p), "l"(v) : "memory");
}
__device__ __forceinline__ float4 ldcg4(const float4* p) {
    float4 v;
    asm volatile("ld.global.cg.v4.f32 {%0,%1,%2,%3}, [%4];"
                 : "=f"(v.x), "=f"(v.y), "=f"(v.z), "=f"(v.w) : "l"(p));
    return v;
}
__device__ __forceinline__ void stcg4(float4* p, float4 v) {
    asm volatile("st.global.cg.v4.f32 [%0], {%1,%2,%3,%4};"
                 :: "l"(p), "f"(v.x), "f"(v.y), "f"(v.z), "f"(v.w) : "memory");
}

__global__ void __launch_bounds__(TPB, 1)
cann_kernel(const float* __restrict__ net_in,
            const float* __restrict__ J,
            float* __restrict__ out)
{
    __shared__ float s_sm[1792];     // s vector (rows 0..1679 used; pad zero)
    __shared__ float s_part[160];    // per-slot partials (148 used; pad zero)
    __shared__ float s_warp[NWARP];  // per-warp s values for the publisher

    const int tid  = threadIdx.x;
    const int lane = tid & 31;
    const int wid  = tid >> 5;
    const int bid  = blockIdx.x;
    const int row  = wid * NB + bid;           // balanced 11-12 rows/block
    const bool active = (row < Nn);

    // Monotonic tag base: own parity-0 slot (last write each run is t=14, parity 0).
    const unsigned base =
        (unsigned)(ld_acq64(&g_pub[0][bid][12]) >> 32);

    // zero the pads once (they are never written again)
    if (tid >= 148 && tid < 160) s_part[tid] = 0.f;
    for (int i = Nn + tid; i < 1792; i += TPB) s_sm[i] = 0.f;

    const float iext = active ? __ldg(&net_in[row]) : 0.f;

    // ---- prologue: J row -> registers (1680 = 13*128 + 16 floats) ----
    float4 Jr[14];
    if (active) {
        const float4* Jp = reinterpret_cast<const float4*>(J + (size_t)row * Nn);
        #pragma unroll
        for (int j = 0; j < 13; ++j) Jr[j] = __ldg(&Jp[j * 32 + lane]);
        Jr[13] = (lane < 4) ? __ldg(&Jp[416 + lane]) : make_float4(0.f,0.f,0.f,0.f);
    }

    float lastS = 0.f, lastU = 0.f;

    for (int t = 1; t <= ITERS; ++t) {
        // ---- acquire s_{t-1} into smem ----
        if (t == 1) {
            const float4* r4 = reinterpret_cast<const float4*>(net_in + Nn);
            for (int i = tid; i < Nn / 4; i += TPB)
                reinterpret_cast<float4*>(s_sm)[i] = __ldg(&r4[i]);
        } else {
            const int par = (t - 1) & 1;
            if (tid < NB) {
                const float* chunk = g_pub[par][tid];
                const unsigned target = base + (unsigned)(t - 1);
                unsigned long long x;
                do { x = ld_acq64(chunk + 12); }
                while ((unsigned)(x >> 32) != target);
                s_part[tid] = __uint_as_float((unsigned)(x & 0xffffffffull));
                float4 c0 = ldcg4((const float4*)(chunk + 0));
                float4 c1 = ldcg4((const float4*)(chunk + 4));
                float4 c2 = ldcg4((const float4*)(chunk + 8));
                s_sm[0*NB + tid]  = c0.x; s_sm[1*NB + tid]  = c0.y;
                s_sm[2*NB + tid]  = c0.z; s_sm[3*NB + tid]  = c0.w;
                s_sm[4*NB + tid]  = c1.x; s_sm[5*NB + tid]  = c1.y;
                s_sm[6*NB + tid]  = c1.z; s_sm[7*NB + tid]  = c1.w;
                s_sm[8*NB + tid]  = c2.x; s_sm[9*NB + tid]  = c2.y;
                s_sm[10*NB + tid] = c2.z; s_sm[11*NB + tid] = c2.w;
            }
        }
        __syncthreads();

        // ---- matvec (register J row  x  smem s) + overlapped recSum reduce ----
        float sval = 0.f;
        if (active) {
            const float4* s4 = reinterpret_cast<const float4*>(s_sm);
            float a0 = 0.f, a1 = 0.f;
            #pragma unroll
            for (int j = 0; j < 13; ++j) {
                float4 b = s4[j * 32 + lane];
                if (j & 1) {
                    a1 = fmaf(Jr[j].x, b.x, a1); a1 = fmaf(Jr[j].y, b.y, a1);
                    a1 = fmaf(Jr[j].z, b.z, a1); a1 = fmaf(Jr[j].w, b.w, a1);
                } else {
                    a0 = fmaf(Jr[j].x, b.x, a0); a0 = fmaf(Jr[j].y, b.y, a0);
                    a0 = fmaf(Jr[j].z, b.z, a0); a0 = fmaf(Jr[j].w, b.w, a0);
                }
            }
            if (lane < 4) {
                float4 b = s4[416 + lane];
                a1 = fmaf(Jr[13].x, b.x, a1); a1 = fmaf(Jr[13].y, b.y, a1);
                a1 = fmaf(Jr[13].z, b.z, a1); a1 = fmaf(Jr[13].w, b.w, a1);
            }
            float acc = a0 + a1;
            // deterministic partial sum of s_{t-1}: fixed slot order, all warps identical
            float rs = ((s_part[lane] + s_part[lane + 32]) +
                        (s_part[lane + 64] + s_part[lane + 96])) + s_part[lane + 128];
            #pragma unroll
            for (int o = 16; o; o >>= 1) {
                acc += __shfl_xor_sync(0xffffffffu, acc, o);
                rs  += __shfl_xor_sync(0xffffffffu, rs,  o);
            }
            if (lane == 0) {
                const float invDen = (t == 1) ? 1.0f : 1.0f / (KC * rs);
                float U  = fmaf(acc, invDen, iext);
                float u2 = 0.2f * U;
                sval = u2 * u2;
                if (t == ITERS) { lastU = U; lastS = sval; }
            }
        }

        // ---- publish: 12 s values + partial + tag, single releasing thread ----
        if (lane == 0) s_warp[wid] = sval;
        __syncthreads();
        if (tid == 0) {
            float4 c0 = make_float4(s_warp[0], s_warp[1], s_warp[2],  s_warp[3]);
            float4 c1 = make_float4(s_warp[4], s_warp[5], s_warp[6],  s_warp[7]);
            float4 c2 = make_float4(s_warp[8], s_warp[9], s_warp[10], s_warp[11]);
            float p = ((c0.x + c0.y) + (c0.z + c0.w)) +
                      ((c1.x + c1.y) + (c1.z + c1.w)) +
                      ((c2.x + c2.y) + (c2.z + c2.w));
            float* dst = g_pub[t & 1][bid];
            stcg4((float4*)(dst + 0), c0);
            stcg4((float4*)(dst + 4), c1);
            stcg4((float4*)(dst + 8), c2);
            unsigned long long pk =
                ((unsigned long long)(base + (unsigned)t) << 32) |
                (unsigned long long)__float_as_uint(p);
            st_rel64(dst + 12, pk);   // release orders the three data stores
        }
        // laggards are held by the next iteration's post-poll __syncthreads
    }

    // ---- epilogue: recSum_14, U_14, r_14 ----
    if (tid < NB) {
        const float* chunk = g_pub[ITERS & 1][tid];
        const unsigned target = base + (unsigned)ITERS;
        unsigned long long x;
        do { x = ld_acq64(chunk + 12); }
        while ((unsigned)(x >> 32) != target);
        s_part[tid] = __uint_as_float((unsigned)(x & 0xffffffffull));
    }
    __syncthreads();
    {
        float rs = ((s_part[lane] + s_part[lane + 32]) +
                    (s_part[lane + 64] + s_part[lane + 96])) + s_part[lane + 128];
        #pragma unroll
        for (int o = 16; o; o >>= 1) rs += __shfl_xor_sync(0xffffffffu, rs, o);
        const float recS = KC * rs;
        if (bid == 0 && tid == 0) out[Nn] = recS;
        if (active && lane == 0) {
            out[row] = lastU;
            out[Nn + 1 + row] = lastS / recS;
        }
    }
}

extern "C" void kernel_launch(void* const* d_in, const int* in_sizes, int n_in,
                              void* d_out, int out_size)
{
    const float* a = (const float*)d_in[0];
    const float* b = (const float*)d_in[1];
    const float* net_in = a;
    const float* J      = b;
    if (n_in >= 2 && in_sizes[0] > in_sizes[1]) { net_in = b; J = a; }
    cann_kernel<<<NB, TPB>>>(net_in, J, (float*)d_out);
}

// round 4
// speedup vs baseline: 1.0378x; 1.0378x over previous
#include <cuda_runtime.h>

// CANN recurrent net, 14 iterations:
//   y_t = J @ s_{t-1};  U_t = y_t/recSum_{t-1} + Iext;  s_t = (0.2 U_t)^2;
//   recSum_t = K * sum(s_t)
// Outputs: U_14 (1680), recSum_14 (1), r_14 = s_14/recSum_14 (1680)
//
// Persistent grid (148 blocks, 1/SM), J rows register-resident (1 warp = 1 row).
// Sync/transfer fused: per-row 64-bit token {tag | s-bits}, parity-buffered,
// tags monotonic across graph replays. Publish = one plain stcg per warp
// (no fences: value rides inside the token). Consumers poll all 1680 tokens.
// recSum is re-derived per warp from the staged s vector during the matvec.

#define Nn     1680
#define NB     148
#define TPB    384
#define ITERS  14
#define KC     0.005f

__device__ unsigned long long g_row[2][Nn];   // {tag:32 | s-bits:32}

__device__ __forceinline__ unsigned long long ldcg64(const unsigned long long* p) {
    unsigned long long v;
    asm volatile("ld.global.cg.u64 %0, [%1];" : "=l"(v) : "l"(p));
    return v;
}
__device__ __forceinline__ void stcg64(unsigned long long* p, unsigned long long v) {
    asm volatile("st.global.cg.u64 [%0], %1;" :: "l"(p), "l"(v) : "memory");
}

// Poll all slots this thread owns (tid, tid+384, ... < 1680) for `target` tag,
// scattering payloads into s_sm as they arrive. Batched loads -> MLP up to 5.
__device__ __forceinline__ void poll_scatter(int par, unsigned target, int tid,
                                             float* s_sm) {
    unsigned long long* slots = g_row[par];
    const unsigned need = (tid < Nn - 4 * TPB) ? 0x1fu : 0x0fu;  // 144 threads own 5
    unsigned done = 0;
    while (done != need) {
        unsigned long long v[5];
        unsigned pend = need & ~done;
        #pragma unroll
        for (int k = 0; k < 5; ++k)
            if (pend & (1u << k)) v[k] = ldcg64(&slots[tid + k * TPB]);
        #pragma unroll
        for (int k = 0; k < 5; ++k)
            if ((pend & (1u << k)) && (unsigned)(v[k] >> 32) == target) {
                s_sm[tid + k * TPB] = __uint_as_float((unsigned)v[k]);
                done |= 1u << k;
            }
    }
}

__global__ void __launch_bounds__(TPB, 1)
cann_kernel(const float* __restrict__ net_in,
            const float* __restrict__ J,
            float* __restrict__ out)
{
    __shared__ __align__(16) float s_sm[Nn];   // staged s vector (6720 B)
    __shared__ float s_recS;

    const int tid  = threadIdx.x;
    const int lane = tid & 31;
    const int wid  = tid >> 5;
    const int bid  = blockIdx.x;
    const int row  = wid * NB + bid;            // balanced 11-12 rows/block
    const bool active = (row < Nn);

    // Monotonic tag base: every parity-0 slot ended the previous run at the
    // same tag (t=14 is parity 0); initial zero state also uniform.
    const unsigned base = (unsigned)(ldcg64(&g_row[0][tid]) >> 32);

    const float iext = active ? __ldg(&net_in[row]) : 0.f;

    // ---- prologue: J row -> registers (1680 = 13*128 + 16 floats) ----
    float4 Jr[14];
    if (active) {
        const float4* Jp = reinterpret_cast<const float4*>(J + (size_t)row * Nn);
        #pragma unroll
        for (int j = 0; j < 13; ++j) Jr[j] = __ldg(&Jp[j * 32 + lane]);
        Jr[13] = (lane < 4) ? __ldg(&Jp[416 + lane]) : make_float4(0.f,0.f,0.f,0.f);
    }

    float lastS = 0.f, lastU = 0.f;

    for (int t = 1; t <= ITERS; ++t) {
        // ---- acquire s_{t-1} into smem (poll doubles as grid barrier) ----
        if (t == 1) {
            const float4* r4 = reinterpret_cast<const float4*>(net_in + Nn);
            for (int i = tid; i < Nn / 4; i += TPB)
                reinterpret_cast<float4*>(s_sm)[i] = __ldg(&r4[i]);
        } else {
            poll_scatter((t - 1) & 1, base + (unsigned)(t - 1), tid, s_sm);
        }
        __syncthreads();

        // ---- matvec (register J x smem s) with fused sum(s_{t-1}) ----
        if (active) {
            const float4* s4 = reinterpret_cast<const float4*>(s_sm);
            float a0 = 0.f, a1 = 0.f, rs = 0.f;
            #pragma unroll
            for (int j = 0; j < 13; ++j) {
                float4 b = s4[j * 32 + lane];
                rs += (b.x + b.y) + (b.z + b.w);
                if (j & 1) {
                    a1 = fmaf(Jr[j].x, b.x, a1); a1 = fmaf(Jr[j].y, b.y, a1);
                    a1 = fmaf(Jr[j].z, b.z, a1); a1 = fmaf(Jr[j].w, b.w, a1);
                } else {
                    a0 = fmaf(Jr[j].x, b.x, a0); a0 = fmaf(Jr[j].y, b.y, a0);
                    a0 = fmaf(Jr[j].z, b.z, a0); a0 = fmaf(Jr[j].w, b.w, a0);
                }
            }
            if (lane < 4) {
                float4 b = s4[416 + lane];
                rs += (b.x + b.y) + (b.z + b.w);
                a1 = fmaf(Jr[13].x, b.x, a1); a1 = fmaf(Jr[13].y, b.y, a1);
                a1 = fmaf(Jr[13].z, b.z, a1); a1 = fmaf(Jr[13].w, b.w, a1);
            }
            float acc = a0 + a1;
            #pragma unroll
            for (int o = 16; o; o >>= 1) {
                acc += __shfl_xor_sync(0xffffffffu, acc, o);
                rs  += __shfl_xor_sync(0xffffffffu, rs,  o);
            }
            // ---- publish this row immediately: value rides inside the token ----
            if (lane == 0) {
                const float invDen = (t == 1) ? 1.0f : 1.0f / (KC * rs);
                float U  = fmaf(acc, invDen, iext);
                float u2 = 0.2f * U;
                float sv = u2 * u2;
                stcg64(&g_row[t & 1][row],
                       ((unsigned long long)(base + (unsigned)t) << 32) |
                       (unsigned long long)__float_as_uint(sv));
                if (t == ITERS) { lastU = U; lastS = sv; }
            }
        }
        // No trailing barrier: the next poll_scatter is the grid barrier, and
        // the __syncthreads after it protects s_sm reuse within the block.
    }

    // ---- epilogue: stage s_14, recSum_14 = K*sum(s_14), write outputs ----
    poll_scatter(ITERS & 1, base + (unsigned)ITERS, tid, s_sm);
    __syncthreads();
    if (wid == 0) {
        const float4* s4 = reinterpret_cast<const float4*>(s_sm);
        float rs = 0.f;
        #pragma unroll
        for (int j = 0; j < 13; ++j) {
            float4 b = s4[j * 32 + lane];
            rs += (b.x + b.y) + (b.z + b.w);
        }
        if (lane < 4) {
            float4 b = s4[416 + lane];
            rs += (b.x + b.y) + (b.z + b.w);
        }
        #pragma unroll
        for (int o = 16; o; o >>= 1) rs += __shfl_xor_sync(0xffffffffu, rs, o);
        if (lane == 0) s_recS = KC * rs;
    }
    __syncthreads();
    const float recS = s_recS;
    if (active && lane == 0) out[row] = lastU;           // U_14
    if (bid == 0) {
        if (tid == 0) out[Nn] = recS;                    // recSum_14
        for (int i = tid; i < Nn; i += TPB)              // r_14
            out[Nn + 1 + i] = s_sm[i] / recS;
    }
}

extern "C" void kernel_launch(void* const* d_in, const int* in_sizes, int n_in,
                              void* d_out, int out_size)
{
    const float* a = (const float*)d_in[0];
    const float* b = (const float*)d_in[1];
    const float* net_in = a;
    const float* J      = b;
    if (n_in >= 2 && in_sizes[0] > in_sizes[1]) { net_in = b; J = a; }
    cann_kernel<<<NB, TPB>>>(net_in, J, (float*)d_out);
}